// round 6
// baseline (speedup 1.0000x reference)
#include <cuda_runtime.h>

#define NN 784
#define GRID 28
#define MAXB 64
#define MAXD2 1459   // d2 in [0, 27^2+27^2=1458]

// Scratch (device globals — no allocations allowed)
__device__ unsigned short g_sort_idx[NN * NN];   // [i][rank] -> neighbor index
__device__ float g_fvals[2 * MAXB * NN];         // [g][m][i] dtm values
__device__ float g_feats[MAXB * 320];            // landscape features per image

__constant__ int c_dxs[8] = {-1, 1, 0, 0, -1, -1, 1, 1};
__constant__ int c_dys[8] = {0, 0, -1, 1, -1, 1, -1, 1};
__constant__ int c_off[8] = {-28, 28, -1, 1, -29, -27, 27, 29};

// ---------------------------------------------------------------------------
// Kernel A: stable argsort of squared grid distances per point (counting sort)
// ---------------------------------------------------------------------------
__global__ void build_sort_table_kernel() {
    int i = blockIdx.x;
    int xi = i / GRID, yi = i % GRID;
    __shared__ unsigned int hist[MAXD2];
    __shared__ unsigned short d2a[NN];
    __shared__ unsigned int wsum[8];
    int tid = threadIdx.x;
    int lane = tid & 31, warp = tid >> 5;

    for (int t = tid; t < MAXD2; t += 256) hist[t] = 0u;
    __syncthreads();
    for (int j = tid; j < NN; j += 256) {
        int dx = j / GRID - xi, dy = j % GRID - yi;
        int d2 = dx * dx + dy * dy;
        d2a[j] = (unsigned short)d2;
        atomicAdd(&hist[d2], 1u);
    }
    __syncthreads();

    // exclusive scan of hist[0..1458] (6 entries per thread, 256 threads)
    unsigned int lv[6];
    unsigned int s = 0u;
    int base = tid * 6;
#pragma unroll
    for (int c = 0; c < 6; c++) {
        unsigned int v = (base + c < MAXD2) ? hist[base + c] : 0u;
        lv[c] = s;
        s += v;
    }
    unsigned int inc = s;
#pragma unroll
    for (int off = 1; off < 32; off <<= 1) {
        unsigned int t = __shfl_up_sync(0xFFFFFFFFu, inc, off);
        if (lane >= off) inc += t;
    }
    if (lane == 31) wsum[warp] = inc;
    __syncthreads();
    if (tid == 0) {
        unsigned int a = 0u;
        for (int w = 0; w < 8; w++) { unsigned int t = wsum[w]; wsum[w] = a; a += t; }
    }
    __syncthreads();
    unsigned int off0 = wsum[warp] + (inc - s);
    __syncthreads();  // all reads of hist done before overwrite
#pragma unroll
    for (int c = 0; c < 6; c++)
        if (base + c < MAXD2) hist[base + c] = off0 + lv[c];
    __syncthreads();

    // Stable scatter: warps serialized in ascending-j order
    for (int gq = 0; gq < 25; gq++) {
        if (warp == (gq & 7)) {
            int j = gq * 32 + lane;
            bool valid = (j < NN);
            unsigned int key = valid ? (unsigned int)d2a[j] : 0xFFFFu;
            unsigned int mk = __match_any_sync(0xFFFFFFFFu, key);
            int leader = __ffs(mk) - 1;
            int pre = __popc(mk & ((1u << lane) - 1u));
            unsigned int b0 = 0u;
            if (lane == leader && valid) b0 = atomicAdd(&hist[key], (unsigned int)__popc(mk));
            b0 = __shfl_sync(0xFFFFFFFFu, b0, leader);
            if (valid) g_sort_idx[i * NN + b0 + pre] = (unsigned short)j;
        }
        __syncthreads();
    }
}

// ---------------------------------------------------------------------------
// Kernel B: DTM for both m0 values in a single pass. Grid (B, 4): 4 blocks/img.
// ---------------------------------------------------------------------------
__global__ void dtm_kernel(const float* __restrict__ x) {
    int m = blockIdx.x;
    __shared__ float img[NN];
    __shared__ float red[8];
    int tid = threadIdx.x;
    int lane = tid & 31, warp = tid >> 5;

    float ps = 0.f;
    for (int j = tid; j < NN; j += 256) {
        float v = x[m * NN + j];
        img[j] = v;
        ps += v;
    }
#pragma unroll
    for (int off = 16; off; off >>= 1) ps += __shfl_xor_sync(0xFFFFFFFFu, ps, off);
    if (lane == 0) red[warp] = ps;
    __syncthreads();
    float S = 0.f;
#pragma unroll
    for (int w = 0; w < 8; w++) S += red[w];
    float bound1 = 0.05f * S;
    float bound2 = 0.2f * S;

    int wglob = blockIdx.y * 8 + warp;   // 32 warps per image
    for (int i = wglob; i < NN; i += 32) {
        int xi = i / GRID, yi = i % GRID;
        float acc1 = 0.f, acc2 = 0.f, running = 0.f;
        for (int c = 0; c < NN; c += 32) {
            int j = c + lane;
            float w = 0.f, fd2 = 0.f;
            if (j < NN) {
                int idx = (int)g_sort_idx[i * NN + j];
                w = img[idx];
                int dx = idx / GRID - xi, dy = idx % GRID - yi;
                fd2 = (float)(dx * dx + dy * dy);
            }
            float cs = w;
#pragma unroll
            for (int off = 1; off < 32; off <<= 1) {
                float t = __shfl_up_sync(0xFFFFFFFFu, cs, off);
                if (lane >= off) cs += t;
            }
            float cumBefore = running + cs - w;
            float e1 = fminf(fmaxf(bound1 - cumBefore, 0.f), w);
            float e2 = fminf(fmaxf(bound2 - cumBefore, 0.f), w);
            acc1 += e1 * fd2;
            acc2 += e2 * fd2;
            running += __shfl_sync(0xFFFFFFFFu, cs, 31);
            if (running >= bound2) break;  // all further eff are exactly 0
        }
#pragma unroll
        for (int off = 16; off; off >>= 1) {
            acc1 += __shfl_xor_sync(0xFFFFFFFFu, acc1, off);
            acc2 += __shfl_xor_sync(0xFFFFFFFFu, acc2, off);
        }
        if (lane == 0) {
            g_fvals[(0 * MAXB + m) * NN + i] = sqrtf(acc1 / bound1);
            g_fvals[(1 * MAXB + m) * NN + i] = sqrtf(acc2 / bound2);
        }
    }
}

// ---------------------------------------------------------------------------
// Kernel C: per-task stable sort (bitonic) + speculative batched union-find
// + fused landscape top-K. One launch: task = blockIdx.x = ((m*2+g)*2+dir).
// ---------------------------------------------------------------------------
struct SmemC {
    unsigned long long keys[1024];
    float vals[NN];
    unsigned order32[NN + 4];        // (yj<<24)|(xj<<16)|j per rank
    unsigned par32[NN];              // root: (birth_pos<<16)|root ; else low16=parent
    unsigned short pos_[NN];
    unsigned char nbm[NN];           // per-rank eligible-neighbor bitmask
    float spB[NN], spD[NN];
};

template <int DIR>
__device__ __forceinline__ void pairs_body(SmemC* s, int g, int m) {
    int tid = threadIdx.x;
    int lane = tid & 31, warp = tid >> 5;
    const unsigned EMASK = DIR ? 0xFFu : 0x0Fu;
    const unsigned INV = 0xFFFFFFFFu;

    for (int j = tid; j < NN; j += 256) {
        float v = g_fvals[(g * MAXB + m) * NN + j];
        s->vals[j] = v;
        float kf = DIR ? -v : v;  // dir1: superlevel via -x
        unsigned int u = __float_as_uint(kf);
        u = (u & 0x80000000u) ? ~u : (u | 0x80000000u);  // sortable transform
        s->keys[j] = ((unsigned long long)u << 32) | (unsigned int)j;  // stable ties by j
        s->spB[j] = 0.f;
        s->spD[j] = 0.f;
    }
    for (int j = NN + tid; j < 1024; j += 256) s->keys[j] = ~0ULL;
    __syncthreads();

    // bitonic sort of 1024 keys
    for (int k = 2; k <= 1024; k <<= 1) {
        for (int jj = k >> 1; jj > 0; jj >>= 1) {
            for (int i = tid; i < 1024; i += 256) {
                int ixj = i ^ jj;
                if (ixj > i) {
                    unsigned long long a = s->keys[i], b = s->keys[ixj];
                    bool up = ((i & k) == 0);
                    if ((a > b) == up) { s->keys[i] = b; s->keys[ixj] = a; }
                }
            }
            __syncthreads();
        }
    }

    for (int r = tid; r < NN; r += 256) {
        int j = (int)(unsigned int)s->keys[r];
        int xj = j / GRID, yj = j % GRID;
        s->order32[r] = (unsigned)j | ((unsigned)xj << 16) | ((unsigned)yj << 24);
        s->pos_[j] = (unsigned short)r;
        s->par32[j] = ((unsigned)r << 16) | (unsigned)j;   // root: birth<<16 | self
    }
    if (tid < 4) s->order32[NN + tid] = 0u;
    __syncthreads();

    // precompute per-rank eligible-neighbor bitmask (pos[u] < r, in bounds)
    for (int r = tid; r < NN; r += 256) {
        unsigned o = s->order32[r];
        int v = (int)(o & 0xFFFFu);
        int xv = (int)((o >> 16) & 0xFFu), yv = (int)(o >> 24);
        unsigned mask = 0u;
#pragma unroll
        for (int l = 0; l < 8; l++) {
            int xu = xv + c_dxs[l], yu = yv + c_dys[l];
            if ((unsigned)xu < (unsigned)GRID && (unsigned)yu < (unsigned)GRID &&
                (int)s->pos_[v + c_off[l]] < r)
                mask |= 1u << l;
        }
        s->nbm[r] = (unsigned char)mask;
    }
    __syncthreads();

    // ---- speculative batched union-find: warp 0. 4 vertices/step, 8 lanes each.
    // packed = (birth_pos<<16)|root; min packed wins; fresh vertex always loses.
    if (tid < 32) {
        volatile unsigned* par = s->par32;
        int k = 0;
        int sub = lane >> 3, sl = lane & 7;
        unsigned lmlt = (1u << lane) - 1u;
        unsigned submask = 0xFFu << (sub << 3);
        for (int base = 0; base < NN; base += 4) {
            unsigned o0 = s->order32[base + 0];
            unsigned o1 = s->order32[base + 1];
            unsigned o2 = s->order32[base + 2];
            unsigned o3 = s->order32[base + 3];
            unsigned em = (unsigned)s->nbm[base + sub] & EMASK;
            unsigned ov = (sub < 2) ? (sub == 0 ? o0 : o1) : (sub == 2 ? o2 : o3);

            // optimistic finds against pre-batch parent state
            unsigned cur = INV;
            if ((em >> sl) & 1u) {
                int xx = (int)(ov & 0xFFFFu) + c_off[sl];
                for (;;) {  // find, 2 levels/iter with path halving
                    unsigned p32 = par[xx];
                    int pl = (int)(p32 & 0xFFFFu);
                    if (pl == xx) { cur = p32; break; }
                    unsigned q32 = par[pl];
                    int ql = (int)(q32 & 0xFFFFu);
                    if (ql == pl) { cur = q32; break; }
                    par[xx] = q32;      // halve: xx -> grandparent
                    xx = ql;
                }
            }

            bool valid = (cur != INV);
            unsigned grp = __match_any_sync(0xFFFFFFFFu, cur);
            // conflict: root shared with another sub, or root born inside batch
            bool conflict = valid && (((grp & ~submask) != 0u) ||
                                      ((cur >> 16) >= (unsigned)base));
            if (__ballot_sync(0xFFFFFFFFu, conflict) == 0u) {
                // ---- fast path: all 4 subs resolve in parallel ----
                unsigned wj = __reduce_min_sync(submask, valid ? cur : INV);
                bool anyv = (wj != INV);
                bool dead = valid && (cur != wj);
                unsigned dmask = __ballot_sync(0xFFFFFFFFu, dead);
                bool leader = dead && ((grp & dmask & lmlt) == 0u);
                unsigned lmask = __ballot_sync(0xFFFFFFFFu, leader);
                if (leader) {
                    par[cur & 0xFFFFu] = wj;
                    int rk = k + __popc(lmask & lmlt);
                    int lbv = (int)(s->order32[cur >> 16] & 0xFFFFu);
                    int vj = (int)(ov & 0xFFFFu);
                    float Bv, Dv;
                    if (DIR == 0) { Bv = s->vals[lbv]; Dv = s->vals[vj]; }
                    else          { Bv = s->vals[vj];  Dv = s->vals[lbv]; }
                    s->spB[rk] = Bv;
                    s->spD[rk] = Dv;
                }
                if (sl == 0 && anyv) par[ov & 0xFFFFu] = wj;
                k += __popc(lmask);
            } else {
                // ---- slow path: exact serial 4-substep fix-up ----
                unsigned pv0 = ((unsigned)(base + 0) << 16) | (o0 & 0xFFFFu);
                unsigned pv1 = ((unsigned)(base + 1) << 16) | (o1 & 0xFFFFu);
                unsigned pv2 = ((unsigned)(base + 2) << 16) | (o2 & 0xFFFFu);
                unsigned pv3 = ((unsigned)(base + 3) << 16) | (o3 & 0xFFFFu);
#pragma unroll
                for (int j = 0; j < 4; j++) {
                    unsigned pvj = (j < 2) ? (j == 0 ? pv0 : pv1) : (j == 2 ? pv2 : pv3);
                    unsigned grp2 = __match_any_sync(0xFFFFFFFFu, cur);
                    bool inj = (sub == j);
                    bool valid2 = (cur != INV);
                    unsigned wj = __reduce_min_sync(0xFFFFFFFFu, (valid2 && inj) ? cur : INV);
                    bool anyv = (wj != INV);
                    bool deadval = inj && valid2 && (cur != wj);
                    unsigned dmask = __ballot_sync(0xFFFFFFFFu, deadval);
                    bool leader = deadval && ((grp2 & dmask & lmlt) == 0u);
                    unsigned lmask = __ballot_sync(0xFFFFFFFFu, leader);
                    unsigned vj = pvj & 0xFFFFu;
                    if (leader) {
                        par[cur & 0xFFFFu] = wj;
                        int rk = k + __popc(lmask & lmlt);
                        int lbv = (int)(s->order32[cur >> 16] & 0xFFFFu);
                        float Bv, Dv;
                        if (DIR == 0) { Bv = s->vals[lbv]; Dv = s->vals[vj]; }
                        else          { Bv = s->vals[vj];  Dv = s->vals[lbv]; }
                        s->spB[rk] = Bv;
                        s->spD[rk] = Dv;
                    }
                    k += __popc(lmask);
                    if (anyv && lane == 0) par[vj] = wj;
                    if (sub > j && valid2) {
                        bool stale = ((grp2 & dmask) != 0u) || (anyv && cur == pvj);
                        if (stale) cur = wj;
                    }
                }
            }
            __syncwarp();
        }
    }
    __syncthreads();

    // ---- fused landscape top-K: 32 t-values, warp per t ----
    int K = g ? 3 : 2;
    float start = g ? 1.0f : 0.0f;
    int fbase = m * 320 + (g ? 128 : 0);
    for (int ti = warp; ti < 32; ti += 8) {
        float t = start + 7.0f * (float)ti / 31.0f;
        float a0 = -1.f, a1 = -1.f, a2 = -1.f;
        for (int j = lane; j < NN; j += 32) {
            float tent = fmaxf(fminf(t - s->spB[j], s->spD[j] - t), 0.f);
            if (tent > a2) {
                if (tent > a0)      { a2 = a1; a1 = a0; a0 = tent; }
                else if (tent > a1) { a2 = a1; a1 = tent; }
                else                { a2 = tent; }
            }
        }
        for (int kk = 0; kk < K; kk++) {
            float w = a0;
#pragma unroll
            for (int off = 16; off; off >>= 1) w = fmaxf(w, __shfl_xor_sync(0xFFFFFFFFu, w, off));
            unsigned bal = __ballot_sync(0xFFFFFFFFu, a0 == w);
            int src = __ffs(bal) - 1;
            if (lane == src) { a0 = a1; a1 = a2; a2 = -1.f; }
            if (lane == 0) g_feats[fbase + (DIR * K + kk) * 32 + ti] = w;
        }
    }
}

__global__ void pairs_kernel() {
    __shared__ SmemC smc;
    int task = blockIdx.x;
    int dir = task & 1;
    int g = (task >> 1) & 1;
    int m = task >> 2;
    if (dir == 0) pairs_body<0>(&smc, g, m);
    else          pairs_body<1>(&smc, g, m);
}

// ---------------------------------------------------------------------------
// Kernel D: tiny MLP. Block per image, 512 threads, warp-per-unit dots.
// ---------------------------------------------------------------------------
__global__ void mlp_kernel(const float* __restrict__ wg1, const float* __restrict__ bg1,
                           const float* __restrict__ wg2, const float* __restrict__ bg2,
                           const float* __restrict__ wfc, const float* __restrict__ bfc,
                           float* __restrict__ out) {
    int m = blockIdx.x;
    __shared__ float sx[64];
    int tid = threadIdx.x;
    int lane = tid & 31, w = tid >> 5;   // 16 warps
    const float* feats = g_feats + m * 320;

#pragma unroll
    for (int i = 0; i < 2; i++) {
        int u = w * 2 + i;
        float a = 0.f;
#pragma unroll
        for (int c = lane; c < 128; c += 32) a += feats[c] * wg1[u * 128 + c];
#pragma unroll
        for (int off = 16; off; off >>= 1) a += __shfl_xor_sync(0xFFFFFFFFu, a, off);
        if (lane == 0) sx[u] = fmaxf(a + bg1[u], 0.f);
    }
#pragma unroll
    for (int i = 0; i < 2; i++) {
        int u = w * 2 + i;
        float a = 0.f;
#pragma unroll
        for (int c = lane; c < 192; c += 32) a += feats[128 + c] * wg2[u * 192 + c];
#pragma unroll
        for (int off = 16; off; off >>= 1) a += __shfl_xor_sync(0xFFFFFFFFu, a, off);
        if (lane == 0) sx[32 + u] = fmaxf(a + bg2[u], 0.f);
    }
    __syncthreads();
    if (tid < 10) {
        float a = bfc[tid];
#pragma unroll
        for (int c = 0; c < 64; c++) a += sx[c] * wfc[tid * 64 + c];
        out[m * 10 + tid] = a;
    }
}

// ---------------------------------------------------------------------------
extern "C" void kernel_launch(void* const* d_in, const int* in_sizes, int n_in,
                              void* d_out, int out_size) {
    const float* x   = (const float*)d_in[0];
    const float* wg1 = (const float*)d_in[1];
    const float* bg1 = (const float*)d_in[2];
    const float* wg2 = (const float*)d_in[3];
    const float* bg2 = (const float*)d_in[4];
    const float* wfc = (const float*)d_in[5];
    const float* bfc = (const float*)d_in[6];
    float* out = (float*)d_out;
    int B = in_sizes[0] / NN;
    if (B > MAXB) B = MAXB;

    build_sort_table_kernel<<<NN, 256>>>();
    dtm_kernel<<<dim3(B, 4), 256>>>(x);
    pairs_kernel<<<B * 4, 256>>>();
    mlp_kernel<<<B, 512>>>(wg1, bg1, wg2, bg2, wfc, bfc, out);
}